// round 2
// baseline (speedup 1.0000x reference)
#include <cuda_runtime.h>
#include <math.h>

// ---------------- problem constants ----------------
#define Bsz 2
#define Tsz 1024
#define Dsz 1024
#define Hn  16
#define HDim 64
#define En  8
#define Kn  2
#define FFn 4096
#define Ntok (Bsz*Tsz)          // 2048
#define NROWS (Ntok*Kn)         // 4096 total expert rows
#define EPSf 1e-5f

// ---------------- scratch (device globals; no allocations) ----------------
__device__ float g_xn  [Ntok*Dsz];        // rmsnorm output (reused twice)
__device__ float g_qkv [Ntok*3*Dsz];      // qkv projection
__device__ float g_attn[Ntok*Dsz];        // attention output (b,t,h,d)
__device__ float g_x1  [Ntok*Dsz];        // x + attn_out
__device__ float g_h   [(size_t)NROWS*FFn]; // MoE hidden (64MB)
__device__ float g_y   [(size_t)NROWS*Dsz]; // per-(token,slot) expert output
__device__ int   g_counts[En];
__device__ int   g_offsets[En];
__device__ int   g_cursor[En];
__device__ int   g_rowmap[NROWS];         // packed token*2+slot per expert row
__device__ int2  g_eidx [Ntok];
__device__ float2 g_gates[Ntok];

// ---------------- rmsnorm ----------------
__global__ void __launch_bounds__(256) rmsnorm_kernel(const float* __restrict__ x,
                                                      const float* __restrict__ scale,
                                                      float* __restrict__ out)
{
    int n = blockIdx.x;
    const float* xr = x + (size_t)n * Dsz;
    float s = 0.f;
    for (int d = threadIdx.x; d < Dsz; d += 256) { float v = xr[d]; s += v * v; }
    // block reduce
    __shared__ float red[8];
    for (int o = 16; o; o >>= 1) s += __shfl_xor_sync(0xffffffffu, s, o);
    if ((threadIdx.x & 31) == 0) red[threadIdx.x >> 5] = s;
    __syncthreads();
    if (threadIdx.x < 32) {
        float v = (threadIdx.x < 8) ? red[threadIdx.x] : 0.f;
        for (int o = 4; o; o >>= 1) v += __shfl_xor_sync(0xffffffffu, v, o);
        if (threadIdx.x == 0) red[0] = v;
    }
    __syncthreads();
    float rms = sqrtf(red[0] / (float)Dsz);
    float inv = 1.0f / (rms + EPSf);
    float* orow = out + (size_t)n * Dsz;
    for (int d = threadIdx.x; d < Dsz; d += 256) orow[d] = xr[d] * inv * scale[d];
}

// ---------------- generic GEMM: C = A[M,K] @ B[K,N] + bias (+resid) ----------------
// BM=128, BN=128, BK=8, 256 threads, 8x8 microtile.
__global__ void __launch_bounds__(256) gemm_bias_kernel(const float* __restrict__ A,
                                                        const float* __restrict__ B,
                                                        const float* __restrict__ bias,
                                                        const float* __restrict__ resid,
                                                        float* __restrict__ C,
                                                        int M, int N, int K)
{
    __shared__ float As[8][128];
    __shared__ float Bs[8][128];
    int tid = threadIdx.x;
    int row0 = blockIdx.y * 128, col0 = blockIdx.x * 128;
    int tx = tid & 15, ty = tid >> 4;
    float acc[8][8];
    #pragma unroll
    for (int i = 0; i < 8; i++)
        #pragma unroll
        for (int j = 0; j < 8; j++) acc[i][j] = 0.f;

    int arow = tid >> 1, ak = (tid & 1) * 4;
    int bk = tid >> 5, bcol = (tid & 31) * 4;
    int gr = row0 + arow;
    bool avalid = gr < M;

    for (int k0 = 0; k0 < K; k0 += 8) {
        float4 av = avalid ? *(const float4*)(A + (size_t)gr * K + k0 + ak)
                           : make_float4(0.f, 0.f, 0.f, 0.f);
        As[ak + 0][arow] = av.x; As[ak + 1][arow] = av.y;
        As[ak + 2][arow] = av.z; As[ak + 3][arow] = av.w;
        *(float4*)&Bs[bk][bcol] = *(const float4*)(B + (size_t)(k0 + bk) * N + col0 + bcol);
        __syncthreads();
        #pragma unroll
        for (int k = 0; k < 8; k++) {
            float a[8], b[8];
            *(float4*)(a)     = *(const float4*)&As[k][ty * 8];
            *(float4*)(a + 4) = *(const float4*)&As[k][ty * 8 + 4];
            *(float4*)(b)     = *(const float4*)&Bs[k][tx * 8];
            *(float4*)(b + 4) = *(const float4*)&Bs[k][tx * 8 + 4];
            #pragma unroll
            for (int i = 0; i < 8; i++)
                #pragma unroll
                for (int j = 0; j < 8; j++) acc[i][j] += a[i] * b[j];
        }
        __syncthreads();
    }
    #pragma unroll
    for (int i = 0; i < 8; i++) {
        int r = row0 + ty * 8 + i;
        if (r < M) {
            #pragma unroll
            for (int j = 0; j < 8; j++) {
                int col = col0 + tx * 8 + j;
                float v = acc[i][j] + bias[col];
                if (resid) v += resid[(size_t)r * N + col];
                C[(size_t)r * N + col] = v;
            }
        }
    }
}

// ---------------- rope (in place on q,k in g_qkv) ----------------
__global__ void __launch_bounds__(256) rope_kernel(float* __restrict__ qkv)
{
    int i = blockIdx.x * 256 + threadIdx.x;   // total Ntok*2*Hn*32
    int j = i & 31;
    int h = (i >> 5) & 15;
    int which = (i >> 9) & 1;
    int n = i >> 10;
    int t = n & (Tsz - 1);
    float theta = powf(10000.0f, -(2.0f * (float)j) / (float)HDim);
    float ang = (float)t * theta;
    float s, c; sincosf(ang, &s, &c);
    float* base = qkv + (size_t)n * (3 * Dsz) + which * Dsz + h * HDim;
    float x1 = base[j], x2 = base[j + 32];
    base[j]      = x1 * c - x2 * s;
    base[j + 32] = x1 * s + x2 * c;
}

// ---------------- flash attention (causal) ----------------
// grid: (T/64, H, B); 256 threads = 8 warps; warp handles 8 queries.
__global__ void __launch_bounds__(256) attn_kernel(const float* __restrict__ qkv,
                                                   float* __restrict__ O)
{
    const int qt = blockIdx.x, h = blockIdx.y, b = blockIdx.z;
    __shared__ float Qs[64][65];
    __shared__ float Ks[32][65];
    __shared__ float Vs[32][65];
    __shared__ float Ps[8][32];
    int tid = threadIdx.x, lane = tid & 31, w = tid >> 5;
    int q0 = qt * 64;

    for (int i = tid; i < 64 * 16; i += 256) {
        int r = i >> 4, c = (i & 15) << 2;
        float4 v = *(const float4*)(qkv + (size_t)(b * Tsz + q0 + r) * (3 * Dsz) + h * HDim + c);
        Qs[r][c] = v.x; Qs[r][c + 1] = v.y; Qs[r][c + 2] = v.z; Qs[r][c + 3] = v.w;
    }

    float acc0[8], acc1[8], m[8], l[8];
    #pragma unroll
    for (int s = 0; s < 8; s++) { acc0[s] = 0.f; acc1[s] = 0.f; m[s] = -1e30f; l[s] = 0.f; }

    int nkt = (q0 + 63) / 32 + 1;
    for (int kt = 0; kt < nkt; kt++) {
        __syncthreads();
        int k0 = kt * 32;
        for (int i = tid; i < 32 * 16; i += 256) {
            int r = i >> 4, c = (i & 15) << 2;
            const float* kb = qkv + (size_t)(b * Tsz + k0 + r) * (3 * Dsz) + Dsz + h * HDim + c;
            float4 kv = *(const float4*)kb;
            Ks[r][c] = kv.x; Ks[r][c + 1] = kv.y; Ks[r][c + 2] = kv.z; Ks[r][c + 3] = kv.w;
            float4 vv = *(const float4*)(kb + Dsz);
            Vs[r][c] = vv.x; Vs[r][c + 1] = vv.y; Vs[r][c + 2] = vv.z; Vs[r][c + 3] = vv.w;
        }
        __syncthreads();
        #pragma unroll
        for (int s = 0; s < 8; s++) {
            int qrow = w * 8 + s;
            int qi = q0 + qrow;
            float sc = 0.f;
            #pragma unroll 16
            for (int d = 0; d < 64; d++) sc += Qs[qrow][d] * Ks[lane][d];
            sc *= 0.125f;
            if (k0 + lane > qi) sc = -1e30f;
            float mt = sc;
            #pragma unroll
            for (int o = 16; o; o >>= 1) mt = fmaxf(mt, __shfl_xor_sync(0xffffffffu, mt, o));
            float mnew = fmaxf(m[s], mt);
            float p = __expf(sc - mnew);
            float ls = p;
            #pragma unroll
            for (int o = 16; o; o >>= 1) ls += __shfl_xor_sync(0xffffffffu, ls, o);
            float alpha = __expf(m[s] - mnew);
            m[s] = mnew;
            l[s] = l[s] * alpha + ls;
            Ps[w][lane] = p;
            __syncwarp();
            float a0 = acc0[s] * alpha, a1 = acc1[s] * alpha;
            #pragma unroll 8
            for (int j = 0; j < 32; j++) {
                float pj = Ps[w][j];
                a0 += pj * Vs[j][lane];
                a1 += pj * Vs[j][lane + 32];
            }
            acc0[s] = a0; acc1[s] = a1;
            __syncwarp();
        }
    }
    #pragma unroll
    for (int s = 0; s < 8; s++) {
        int qi = q0 + w * 8 + s;
        float inv = 1.0f / l[s];
        size_t o = (size_t)(b * Tsz + qi) * Dsz + h * HDim;
        O[o + lane]      = acc0[s] * inv;
        O[o + lane + 32] = acc1[s] * inv;
    }
}

// ---------------- MoE routing ----------------
__global__ void moe_init_kernel()
{
    int i = threadIdx.x;
    if (i < En) { g_counts[i] = 0; g_cursor[i] = 0; }
}

__global__ void __launch_bounds__(256) gate_kernel(const float* __restrict__ xn,
                                                   const float* __restrict__ w_gate,
                                                   const float* __restrict__ b_gate)
{
    int n = blockIdx.x * 8 + (threadIdx.x >> 5);
    int lane = threadIdx.x & 31;
    float acc[En];
    #pragma unroll
    for (int e = 0; e < En; e++) acc[e] = 0.f;
    const float* xr = xn + (size_t)n * Dsz;
    for (int d = lane; d < Dsz; d += 32) {
        float xv = xr[d];
        const float* wr = w_gate + (size_t)d * En;
        #pragma unroll
        for (int e = 0; e < En; e++) acc[e] += xv * wr[e];
    }
    #pragma unroll
    for (int e = 0; e < En; e++)
        #pragma unroll
        for (int o = 16; o; o >>= 1) acc[e] += __shfl_xor_sync(0xffffffffu, acc[e], o);
    if (lane == 0) {
        #pragma unroll
        for (int e = 0; e < En; e++) acc[e] += b_gate[e];
        int e0 = 0; float v0 = acc[0];
        #pragma unroll
        for (int e = 1; e < En; e++) if (acc[e] > v0) { v0 = acc[e]; e0 = e; }
        int e1 = -1; float v1 = -1e30f;
        #pragma unroll
        for (int e = 0; e < En; e++) if (e != e0 && acc[e] > v1) { v1 = acc[e]; e1 = e; }
        float g0 = 1.0f / (1.0f + __expf(v1 - v0));
        float g1 = 1.0f - g0;
        atomicAdd(&g_counts[e0], 1);
        atomicAdd(&g_counts[e1], 1);
        g_eidx[n] = make_int2(e0, e1);
        g_gates[n] = make_float2(g0, g1);
    }
}

__global__ void moe_offsets_kernel(float* __restrict__ aux_out)
{
    if (threadIdx.x == 0) {
        int off = 0;
        float aux = 0.f;
        #pragma unroll
        for (int e = 0; e < En; e++) { g_offsets[e] = off; off += g_counts[e]; }
        #pragma unroll
        for (int e = 0; e < En; e++) {
            float f = (float)g_counts[e] / (float)NROWS - 1.0f / (float)En;
            aux += f * f;
        }
        *aux_out = aux;
    }
}

__global__ void __launch_bounds__(256) moe_scatter_kernel()
{
    int n = blockIdx.x * 256 + threadIdx.x;
    if (n >= Ntok) return;
    int2 e = g_eidx[n];
    int p0 = atomicAdd(&g_cursor[e.x], 1);
    g_rowmap[g_offsets[e.x] + p0] = n * 2;
    int p1 = atomicAdd(&g_cursor[e.y], 1);
    g_rowmap[g_offsets[e.y] + p1] = n * 2 + 1;
}

// ---------------- MoE GEMM 1: H = silu(X@W1+b1) * (X@W2+b2) ----------------
// BM=128, BN=64, BK=8, 256 threads, dual 8x4 microtiles. grid: (FF/64, 32, E)
__global__ void __launch_bounds__(256) moe_gemm1_kernel(const float* __restrict__ xn,
                                                        const float* __restrict__ w1,
                                                        const float* __restrict__ b1,
                                                        const float* __restrict__ w2,
                                                        const float* __restrict__ b2)
{
    int e = blockIdx.z;
    int cnt = g_counts[e];
    int row0 = blockIdx.y * 128;
    if (row0 >= cnt) return;
    int off = g_offsets[e];
    int col0 = blockIdx.x * 64;

    __shared__ float As[8][128];
    __shared__ float B1s[8][64];
    __shared__ float B2s[8][64];
    __shared__ int toks[128];

    int tid = threadIdx.x;
    if (tid < 128) {
        int r = row0 + tid;
        toks[tid] = (r < cnt) ? (g_rowmap[off + r] >> 1) : -1;
    }
    __syncthreads();

    const float* W1 = w1 + (size_t)e * Dsz * FFn;
    const float* W2 = w2 + (size_t)e * Dsz * FFn;
    int tx = tid & 15, ty = tid >> 4;
    float c1[8][4], c2[8][4];
    #pragma unroll
    for (int i = 0; i < 8; i++)
        #pragma unroll
        for (int j = 0; j < 4; j++) { c1[i][j] = 0.f; c2[i][j] = 0.f; }

    int arow = tid >> 1, ak = (tid & 1) * 4;
    int bk = tid >> 5, bcol = (tid & 31) * 2;
    int atok = toks[arow];

    for (int k0 = 0; k0 < Dsz; k0 += 8) {
        float4 av = (atok >= 0) ? *(const float4*)(xn + (size_t)atok * Dsz + k0 + ak)
                                : make_float4(0.f, 0.f, 0.f, 0.f);
        As[ak + 0][arow] = av.x; As[ak + 1][arow] = av.y;
        As[ak + 2][arow] = av.z; As[ak + 3][arow] = av.w;
        *(float2*)&B1s[bk][bcol] = *(const float2*)(W1 + (size_t)(k0 + bk) * FFn + col0 + bcol);
        *(float2*)&B2s[bk][bcol] = *(const float2*)(W2 + (size_t)(k0 + bk) * FFn + col0 + bcol);
        __syncthreads();
        #pragma unroll
        for (int k = 0; k < 8; k++) {
            float a[8], u[4], v[4];
            *(float4*)(a)     = *(const float4*)&As[k][ty * 8];
            *(float4*)(a + 4) = *(const float4*)&As[k][ty * 8 + 4];
            *(float4*)u = *(const float4*)&B1s[k][tx * 4];
            *(float4*)v = *(const float4*)&B2s[k][tx * 4];
            #pragma unroll
            for (int i = 0; i < 8; i++)
                #pragma unroll
                for (int j = 0; j < 4; j++) {
                    c1[i][j] += a[i] * u[j];
                    c2[i][j] += a[i] * v[j];
                }
        }
        __syncthreads();
    }
    #pragma unroll
    for (int i = 0; i < 8; i++) {
        int r = row0 + ty * 8 + i;
        if (r < cnt) {
            size_t grow = (size_t)(off + r);
            #pragma unroll
            for (int j = 0; j < 4; j++) {
                int col = col0 + tx * 4 + j;
                float aa = c1[i][j] + b1[e * FFn + col];
                float bb = c2[i][j] + b2[e * FFn + col];
                float s = aa / (1.0f + __expf(-aa));
                g_h[grow * FFn + col] = s * bb;
            }
        }
    }
}

// ---------------- MoE GEMM 2: Y = H @ Wp + bp (scatter to (token,slot)) ----------------
// grid: (D/128, 32, E)
__global__ void __launch_bounds__(256) moe_gemm2_kernel(const float* __restrict__ wp,
                                                        const float* __restrict__ bp)
{
    int e = blockIdx.z;
    int cnt = g_counts[e];
    int row0 = blockIdx.y * 128;
    if (row0 >= cnt) return;
    int off = g_offsets[e];
    int col0 = blockIdx.x * 128;
    const float* B = wp + (size_t)e * FFn * Dsz;

    __shared__ float As[8][128];
    __shared__ float Bs[8][128];
    int tid = threadIdx.x;
    int tx = tid & 15, ty = tid >> 4;
    float acc[8][8];
    #pragma unroll
    for (int i = 0; i < 8; i++)
        #pragma unroll
        for (int j = 0; j < 8; j++) acc[i][j] = 0.f;

    int arow = tid >> 1, ak = (tid & 1) * 4;
    int bk = tid >> 5, bcol = (tid & 31) * 4;
    bool avalid = (row0 + arow) < cnt;
    const float* Arow = g_h + (size_t)(off + row0 + arow) * FFn;

    for (int k0 = 0; k0 < FFn; k0 += 8) {
        float4 av = avalid ? *(const float4*)(Arow + k0 + ak) : make_float4(0.f, 0.f, 0.f, 0.f);
        As[ak + 0][arow] = av.x; As[ak + 1][arow] = av.y;
        As[ak + 2][arow] = av.z; As[ak + 3][arow] = av.w;
        *(float4*)&Bs[bk][bcol] = *(const float4*)(B + (size_t)(k0 + bk) * Dsz + col0 + bcol);
        __syncthreads();
        #pragma unroll
        for (int k = 0; k < 8; k++) {
            float a[8], b[8];
            *(float4*)(a)     = *(const float4*)&As[k][ty * 8];
            *(float4*)(a + 4) = *(const float4*)&As[k][ty * 8 + 4];
            *(float4*)(b)     = *(const float4*)&Bs[k][tx * 8];
            *(float4*)(b + 4) = *(const float4*)&Bs[k][tx * 8 + 4];
            #pragma unroll
            for (int i = 0; i < 8; i++)
                #pragma unroll
                for (int j = 0; j < 8; j++) acc[i][j] += a[i] * b[j];
        }
        __syncthreads();
    }
    #pragma unroll
    for (int i = 0; i < 8; i++) {
        int r = row0 + ty * 8 + i;
        if (r < cnt) {
            int packed = g_rowmap[off + r];   // token*2 + slot
            float* yrow = g_y + (size_t)packed * Dsz;
            #pragma unroll
            for (int j = 0; j < 8; j++) {
                int col = col0 + tx * 8 + j;
                yrow[col] = acc[i][j] + bp[e * Dsz + col];
            }
        }
    }
}

// ---------------- final combine ----------------
__global__ void __launch_bounds__(256) combine_kernel(const float* __restrict__ x1,
                                                      float* __restrict__ out)
{
    int i = blockIdx.x * 256 + threadIdx.x;   // < Ntok*Dsz
    int n = i >> 10;
    int d = i & 1023;
    float2 g = g_gates[n];
    float y0 = g_y[(size_t)(n * 2) * Dsz + d];
    float y1 = g_y[(size_t)(n * 2 + 1) * Dsz + d];
    out[i] = x1[i] + g.x * y0 + g.y * y1;
}

// ---------------- launch ----------------
extern "C" void kernel_launch(void* const* d_in, const int* in_sizes, int n_in,
                              void* d_out, int out_size)
{
    const float* x      = (const float*)d_in[0];
    const float* w_qkv  = (const float*)d_in[1];
    const float* b_qkv  = (const float*)d_in[2];
    const float* w_out  = (const float*)d_in[3];
    const float* b_out  = (const float*)d_in[4];
    const float* scale1 = (const float*)d_in[5];
    const float* scale2 = (const float*)d_in[6];
    const float* w_gate = (const float*)d_in[7];
    const float* b_gate = (const float*)d_in[8];
    const float* w1     = (const float*)d_in[9];
    const float* b1     = (const float*)d_in[10];
    const float* w2     = (const float*)d_in[11];
    const float* b2     = (const float*)d_in[12];
    const float* wp     = (const float*)d_in[13];
    const float* bp     = (const float*)d_in[14];
    float* out = (float*)d_out;

    float* xn   = nullptr; cudaGetSymbolAddress((void**)&xn,   g_xn);
    float* qkv  = nullptr; cudaGetSymbolAddress((void**)&qkv,  g_qkv);
    float* attn = nullptr; cudaGetSymbolAddress((void**)&attn, g_attn);
    float* x1   = nullptr; cudaGetSymbolAddress((void**)&x1,   g_x1);

    // 1. xn = rmsnorm(x, scale1)
    rmsnorm_kernel<<<Ntok, 256>>>(x, scale1, xn);
    // 2. qkv = xn @ w_qkv + b_qkv
    gemm_bias_kernel<<<dim3(3 * Dsz / 128, Ntok / 128), 256>>>(xn, w_qkv, b_qkv, nullptr, qkv,
                                                               Ntok, 3 * Dsz, Dsz);
    // 3. rope on q,k
    rope_kernel<<<(Ntok * 2 * Hn * 32) / 256, 256>>>(qkv);
    // 4. attention
    attn_kernel<<<dim3(Tsz / 64, Hn, Bsz), 256>>>(qkv, attn);
    // 5. x1 = attn @ w_out + b_out + x
    gemm_bias_kernel<<<dim3(Dsz / 128, Ntok / 128), 256>>>(attn, w_out, b_out, x, x1,
                                                           Ntok, Dsz, Dsz);
    // 6. xn = rmsnorm(x1, scale2)
    rmsnorm_kernel<<<Ntok, 256>>>(x1, scale2, xn);
    // 7-10. routing
    moe_init_kernel<<<1, 32>>>();
    gate_kernel<<<Ntok / 8, 256>>>(xn, w_gate, b_gate);
    moe_offsets_kernel<<<1, 32>>>(out + (out_size - 1));
    moe_scatter_kernel<<<(Ntok + 255) / 256, 256>>>();
    // 11. H = silu(X@W1+b1)*(X@W2+b2)
    moe_gemm1_kernel<<<dim3(FFn / 64, NROWS / 128, En), 256>>>(xn, w1, b1, w2, b2);
    // 12. Y = H@Wp + bp
    moe_gemm2_kernel<<<dim3(Dsz / 128, NROWS / 128, En), 256>>>(wp, bp);
    // 13. out = x1 + g0*Y0 + g1*Y1
    combine_kernel<<<(Ntok * Dsz) / 256, 256>>>(x1, out);
}